// round 14
// baseline (speedup 1.0000x reference)
#include <cuda_runtime.h>
#include <cuda_bf16.h>
#include <math.h>

#define VOCABN 32000
#define EMBN   512
#define HIDN   1024
#define BN     64
#define SEQN   64
#define G3N    3072
#define NT2    125   /* 32000 / 256 vocab tiles */
#define GHB    96    /* gh blocks: 24 n x 4 k-splits */

typedef unsigned long long ull;
typedef unsigned int u32;

struct Part { float mx, se, bk, bkl, bg, bgl; int bki, bgi; };

// ---------------- device scratch (no allocations allowed) -------------------
__device__ float d_h[2][BN * HIDN];
__device__ int   d_samp[BN];
__device__ float d_pgi[4][BN * G3N];
__device__ float d_pgh[4][BN * G3N];
__device__ Part  d_part[NT2 * BN];
__device__ u32   d_cnt;
// packed, SW128-swizzled bf16 tiles for the logits GEMM
__device__ __align__(128) char d_wpk[(size_t)NT2 * 16 * 65536];
__device__ __align__(128) char d_hpk[16 * 16384];

// ---------------- f32x2 packed helpers ---------------------------------------
__device__ __forceinline__ ull pack2(float lo, float hi) {
    ull r; asm("mov.b64 %0, {%1, %2};" : "=l"(r) : "f"(lo), "f"(hi)); return r;
}
__device__ __forceinline__ void unpack2(ull v, float& lo, float& hi) {
    asm("mov.b64 {%0, %1}, %2;" : "=f"(lo), "=f"(hi) : "l"(v));
}
__device__ __forceinline__ void fma2(ull& d, ull a, ull b) {
    asm("fma.rn.f32x2 %0, %1, %2, %0;" : "+l"(d) : "l"(a), "l"(b));
}

// ---------------- mma.sync / bulk-copy helpers -------------------------------
__device__ __forceinline__ u32 smem_u32(const void* p) {
    u32 a; asm("{ .reg .u64 t; cvta.to.shared.u64 t, %1; cvt.u32.u64 %0, t; }"
               : "=r"(a) : "l"(p));
    return a;
}
__device__ __forceinline__ void ldmA4(u32 a, u32* r) {
    asm volatile("ldmatrix.sync.aligned.m8n8.x4.shared.b16 {%0,%1,%2,%3}, [%4];"
                 : "=r"(r[0]), "=r"(r[1]), "=r"(r[2]), "=r"(r[3]) : "r"(a));
}
__device__ __forceinline__ void ldmB2(u32 a, u32* r) {
    asm volatile("ldmatrix.sync.aligned.m8n8.x2.shared.b16 {%0,%1}, [%2];"
                 : "=r"(r[0]), "=r"(r[1]) : "r"(a));
}
__device__ __forceinline__ void mma16816(float* c, const u32* a, const u32* b) {
    asm volatile(
        "mma.sync.aligned.m16n8k16.row.col.f32.bf16.bf16.f32 "
        "{%0,%1,%2,%3}, {%4,%5,%6,%7}, {%8,%9}, {%0,%1,%2,%3};"
        : "+f"(c[0]), "+f"(c[1]), "+f"(c[2]), "+f"(c[3])
        : "r"(a[0]), "r"(a[1]), "r"(a[2]), "r"(a[3]), "r"(b[0]), "r"(b[1]));
}
__device__ __forceinline__ void bulkcp(u32 dst, const void* src, u32 bytes, u32 mbar) {
    asm volatile(
        "cp.async.bulk.shared::cta.global.mbarrier::complete_tx::bytes [%0], [%1], %2, [%3];"
        :: "r"(dst), "l"(src), "r"(bytes), "r"(mbar) : "memory");
}
#define MB_INIT(mbar, cnt) \
    asm volatile("mbarrier.init.shared.b64 [%0], %1;" :: "r"(mbar), "r"(cnt) : "memory")
#define MB_EXPECT(mbar, bytes) \
    asm volatile("mbarrier.arrive.expect_tx.shared.b64 _, [%0], %1;" :: "r"(mbar), "r"(bytes) : "memory")
#define MB_WAIT(mbar, parity) do { \
    asm volatile( \
        "{\n\t.reg .pred P1;\n\t" \
        "WL_%=:\n\t" \
        "mbarrier.try_wait.parity.acquire.cta.shared::cta.b64 P1, [%0], %1, 0x989680;\n\t" \
        "@P1 bra.uni WD_%=;\n\t" \
        "bra.uni WL_%=;\n\t" \
        "WD_%=:\n\t}" \
        :: "r"(mbar), "r"(parity) : "memory"); \
} while (0)

// swizzle: XOR 16B-segment index with (row & 7)
__device__ __forceinline__ u32 swz(int row, int colbyte) {
    return (u32)(row * 128 + (colbyte ^ ((row & 7) << 4)));
}

// ---------------- init: also zero d_pgh (step-0 gh with h0=0) ----------------
__global__ void k_init() {
    int i = blockIdx.x * blockDim.x + threadIdx.x;
    if (i < BN * HIDN) d_h[0][i] = 0.f;
    if (i < BN) d_samp[i] = 0;
    if (i == 0) d_cnt = 0;
    if (i < 16 * 16384 / 16) {
        uint4 z; z.x = z.y = z.z = z.w = 0;
        *(uint4*)(d_hpk + i * 16) = z;
    }
    float* pgh = &d_pgh[0][0];
    for (int j = i; j < 4 * BN * G3N; j += gridDim.x * blockDim.x) pgh[j] = 0.f;
}

// ---------------- pack w_out -> chunk-major swizzled bf16 hi/lo --------------
__global__ void k_splitpack(const float* __restrict__ w_out) {
    long n = (long)NT2 * 16 * 256 * 64;
    long i = (long)blockIdx.x * blockDim.x + threadIdx.x;
    long stride = (long)gridDim.x * blockDim.x;
    for (; i < n; i += stride) {
        int k = (int)(i & 63);
        long r2 = i >> 6;   int r = (int)(r2 & 255);
        long c2 = r2 >> 8;  int c = (int)(c2 & 15);
        int v = (int)(c2 >> 4);
        float x = w_out[((size_t)(v * 256 + r)) * HIDN + c * 64 + k];
        __nv_bfloat16 hi = __float2bfloat16_rn(x);
        float l = x - __bfloat162float(hi);
        size_t blk = ((size_t)v * 16 + c) * 65536;
        u32 off = swz(r, k * 2);
        *(__nv_bfloat16*)(d_wpk + blk + off)         = hi;
        *(__nv_bfloat16*)(d_wpk + blk + 32768 + off) = __float2bfloat16_rn(l);
    }
}

// ---------------- gi partial GEMM: emb[samp]@w_ih^T (K-split 4) --------------
__global__ __launch_bounds__(256) void k_gi(const float* __restrict__ emb,
                                            const float* __restrict__ w) {
    __shared__ int ss[BN];
    __shared__ __align__(16) float As[64][36];
    __shared__ __align__(16) float Bs[32][130];
    int tid = threadIdx.x, tx = tid & 15, ty = tid >> 4;
    int nBase = blockIdx.x * 128;
    int kBase = blockIdx.y * 128;
    if (tid < BN) ss[tid] = d_samp[tid];
    __syncthreads();

    ull acc[4][4];
    ull z0 = pack2(0.f, 0.f);
#pragma unroll
    for (int i = 0; i < 4; i++)
#pragma unroll
        for (int jj = 0; jj < 4; jj++) acc[i][jj] = z0;

    for (int kt = 0; kt < 4; kt++) {
        int k0 = kBase + kt * 32;
#pragma unroll
        for (int it = 0; it < 2; it++) {
            int idx = tid + it * 256, row = idx >> 3, k4 = (idx & 7) << 2;
            *(float4*)&As[row][k4] =
                *(const float4*)(emb + (size_t)ss[row] * EMBN + k0 + k4);
        }
#pragma unroll
        for (int it = 0; it < 4; it++) {
            int idx = tid + it * 256, row = idx >> 3, k4 = (idx & 7) << 2;
            float4 v = *(const float4*)(w + (size_t)(nBase + row) * EMBN + k0 + k4);
            Bs[k4+0][row] = v.x; Bs[k4+1][row] = v.y;
            Bs[k4+2][row] = v.z; Bs[k4+3][row] = v.w;
        }
        __syncthreads();
#pragma unroll
        for (int kk = 0; kk < 32; kk++) {
            ull a2[4], b2[4];
#pragma unroll
            for (int jj = 0; jj < 4; jj++)
                b2[jj] = *(const ull*)&Bs[kk][2 * (tx + 16 * jj)];
#pragma unroll
            for (int i = 0; i < 4; i++) { float a = As[ty*4+i][kk]; a2[i] = pack2(a, a); }
#pragma unroll
            for (int i = 0; i < 4; i++)
#pragma unroll
                for (int jj = 0; jj < 4; jj++) fma2(acc[i][jj], a2[i], b2[jj]);
        }
        __syncthreads();
    }
    float* dst = d_pgi[blockIdx.y];
#pragma unroll
    for (int i = 0; i < 4; i++) { int m = ty * 4 + i;
#pragma unroll
        for (int jj = 0; jj < 4; jj++) {
            float lo, hi; unpack2(acc[i][jj], lo, hi);
            float2 vv; vv.x = lo; vv.y = hi;
            *(float2*)&dst[m * G3N + nBase + 2 * (tx + 16 * jj)] = vv;
        }
    }
}

// ---------------- GRU gate combine -> h_new (+ packed bf16 hi/lo) -----------
__global__ void k_combine(const float* __restrict__ b_ih,
                          const float* __restrict__ b_hh, int hb) {
    int idx = blockIdx.x * blockDim.x + threadIdx.x;
    if (idx >= BN * HIDN) return;
    int b = idx >> 10, j = idx & 1023;
    int base = b * G3N;
    float gir = b_ih[j], giz = b_ih[j + HIDN], gin = b_ih[j + 2 * HIDN];
    float ghr = b_hh[j], ghz = b_hh[j + HIDN], ghn = b_hh[j + 2 * HIDN];
#pragma unroll
    for (int ks = 0; ks < 4; ks++) {
        gir += d_pgi[ks][base + j];
        giz += d_pgi[ks][base + j + HIDN];
        gin += d_pgi[ks][base + j + 2 * HIDN];
    }
#pragma unroll
    for (int ks = 0; ks < 4; ks++) {
        ghr += d_pgh[ks][base + j];
        ghz += d_pgh[ks][base + j + HIDN];
        ghn += d_pgh[ks][base + j + 2 * HIDN];
    }
    float r = 1.f / (1.f + expf(-(gir + ghr)));
    float z = 1.f / (1.f + expf(-(giz + ghz)));
    float n = tanhf(gin + r * ghn);
    float hp = d_h[hb][idx];
    float hn = (1.f - z) * n + z * hp;
    d_h[hb ^ 1][idx] = hn;
    __nv_bfloat16 hi = __float2bfloat16_rn(hn);
    float lo = hn - __bfloat162float(hi);
    int chk = j >> 6, kk = j & 63;
    u32 off = swz(b, kk * 2);
    *(__nv_bfloat16*)(d_hpk + chk * 16384 + off)        = hi;
    *(__nv_bfloat16*)(d_hpk + chk * 16384 + 8192 + off) = __float2bfloat16_rn(lo);
}

// ---------------- merge helper ------------------------------------------------
__device__ __forceinline__ void mergeP(Part& a, const Part& o) {
    float nm = fmaxf(a.mx, o.mx);
    a.se = a.se * expf(a.mx - nm) + o.se * expf(o.mx - nm);
    a.mx = nm;
    if (o.bk > a.bk || (o.bk == a.bk && o.bki < a.bki)) { a.bk = o.bk; a.bki = o.bki; a.bkl = o.bkl; }
    if (o.bg > a.bg || (o.bg == a.bg && o.bgi < a.bgi)) { a.bg = o.bg; a.bgi = o.bgi; a.bgl = o.bgl; }
}

// ---------------- gh GEMM as a device block function (512 thr) ---------------
// blocks compute d_pgh[kb] = h(next) @ w_hh^T slice, tile 64 x 128, K = 256
__device__ void gh_block(int bid2, int hbn, const float* __restrict__ w_hh,
                         char* smem) {
    float (*As)[36]  = (float(*)[36])(smem);           // 9216 B
    float (*Bs)[130] = (float(*)[130])(smem + 9216);   // 16640 B
    int tid = threadIdx.x, tx = tid & 15, ty = tid >> 4;   // ty 0..31
    int nBase = (bid2 % 24) * 128;
    int kb = bid2 / 24;                                 // 0..3
    int kBase = kb * 256;
    const float* h = d_h[hbn];

    ull acc[2][4];
    ull z0 = pack2(0.f, 0.f);
#pragma unroll
    for (int i = 0; i < 2; i++)
#pragma unroll
        for (int jj = 0; jj < 4; jj++) acc[i][jj] = z0;

    for (int kt = 0; kt < 8; kt++) {
        int k0 = kBase + kt * 32;
        {
            int row = tid >> 3, k4 = (tid & 7) << 2;   // 512 = 64 rows x 8 q
            *(float4*)&As[row][k4] = *(const float4*)(h + row * HIDN + k0 + k4);
        }
#pragma unroll
        for (int it = 0; it < 2; it++) {
            int idx = tid + it * 512, row = idx >> 3, k4 = (idx & 7) << 2;
            float4 v = *(const float4*)(w_hh + (size_t)(nBase + row) * HIDN + k0 + k4);
            Bs[k4+0][row] = v.x; Bs[k4+1][row] = v.y;
            Bs[k4+2][row] = v.z; Bs[k4+3][row] = v.w;
        }
        __syncthreads();
#pragma unroll
        for (int kk = 0; kk < 32; kk++) {
            ull a2[2], b2[4];
#pragma unroll
            for (int jj = 0; jj < 4; jj++)
                b2[jj] = *(const ull*)&Bs[kk][2 * (tx + 16 * jj)];
#pragma unroll
            for (int i = 0; i < 2; i++) { float a = As[ty*2+i][kk]; a2[i] = pack2(a, a); }
#pragma unroll
            for (int i = 0; i < 2; i++)
#pragma unroll
                for (int jj = 0; jj < 4; jj++) fma2(acc[i][jj], a2[i], b2[jj]);
        }
        __syncthreads();
    }
    float* dst = d_pgh[kb];
#pragma unroll
    for (int i = 0; i < 2; i++) { int m = ty * 2 + i;
#pragma unroll
        for (int jj = 0; jj < 4; jj++) {
            float lo, hi; unpack2(acc[i][jj], lo, hi);
            float2 vv; vv.x = lo; vv.y = hi;
            *(float2*)&dst[m * G3N + nBase + 2 * (tx + 16 * jj)] = vv;
        }
    }
}

// ---------------- logits (blocks 0..124) + gh-for-next-step (125..220) ------
#define STG_BYTES 81920
#define OFF_MB   (2 * STG_BYTES)
#define OFF_BO   (OFF_MB + 16)
#define OFF_PART (OFF_BO + 1024 + 16)
#define SMEM_LOG (OFF_PART + 64 * 4 * (int)sizeof(Part))

__global__ __launch_bounds__(512) void k_logits(const float* __restrict__ b_out,
                                                const float* __restrict__ gu,
                                                const float* __restrict__ eps_u,
                                                const float* __restrict__ w_hh,
                                                float* __restrict__ out,
                                                int t, int hbn, int dogh) {
    extern __shared__ __align__(128) char smem[];
    __shared__ u32 isLast;
    if (blockIdx.x >= NT2) {
        if (dogh) gh_block(blockIdx.x - NT2, hbn, w_hh, smem);
        return;
    }
    u32 sbase = smem_u32(smem);
    int tid = threadIdx.x, lane = tid & 31, wid = tid >> 5;
    int mw = wid >> 2, nw = wid & 3;           // 4 x 4 warp grid
    int mrow = mw * 16, ncol = nw * 64;
    int vBase = blockIdx.x * 256;

    float* bo = (float*)(smem + OFF_BO);
    Part* parts = (Part*)(smem + OFF_PART);
    if (tid < 256) bo[tid] = b_out[vBase + tid];
    if (tid == 0) {
        MB_INIT(sbase + OFF_MB, 1u);
        MB_INIT(sbase + OFF_MB + 8, 1u);
    }
    __syncthreads();

    const char* wblk = d_wpk + (size_t)blockIdx.x * 16 * 65536;
    if (tid == 0) {
#pragma unroll
        for (int s = 0; s < 2; s++) {
            u32 mb = sbase + OFF_MB + s * 8;
            MB_EXPECT(mb, STG_BYTES);
            bulkcp(sbase + s * STG_BYTES,         d_hpk + s * 16384, 16384, mb);
            bulkcp(sbase + s * STG_BYTES + 16384, wblk + (size_t)s * 65536, 65536, mb);
        }
    }

    int lrA = lane & 15;
    u32 xorA = (u32)(lane & 7) << 4;
    u32 colA0 = (u32)((lane >> 4) << 4);
    int lrB = lane & 7;
    u32 xorB = (u32)(lane & 7) << 4;
    u32 colB0 = (u32)(((lane >> 3) & 1) << 4);

    float acc[8][4];
#pragma unroll
    for (int j = 0; j < 8; j++)
#pragma unroll
        for (int k = 0; k < 4; k++) acc[j][k] = 0.f;

    for (int c = 0; c < 16; c++) {
        int st = c & 1;
        u32 mb = sbase + OFF_MB + st * 8;
        MB_WAIT(mb, (c >> 1) & 1);
        u32 Asm = sbase + st * STG_BYTES;
        u32 Bsm = Asm + 16384;
#pragma unroll
        for (int ks = 0; ks < 4; ks++) {
            u32 kb = ks * 32;
            u32 ah[4], al[4], bh[8][2], bl[8][2];
            u32 ra = (u32)((mrow + lrA) * 128) + ((kb + colA0) ^ xorA);
            ldmA4(Asm + ra, ah);
            ldmA4(Asm + 8192 + ra, al);
#pragma unroll
            for (int nt = 0; nt < 8; nt++) {
                u32 rb = (u32)((ncol + nt * 8 + lrB) * 128) + ((kb + colB0) ^ xorB);
                ldmB2(Bsm + rb, bh[nt]);
                ldmB2(Bsm + 32768 + rb, bl[nt]);
            }
#pragma unroll
            for (int nt = 0; nt < 8; nt++) mma16816(acc[nt], ah, bh[nt]);
#pragma unroll
            for (int nt = 0; nt < 8; nt++) mma16816(acc[nt], ah, bl[nt]);
#pragma unroll
            for (int nt = 0; nt < 8; nt++) mma16816(acc[nt], al, bh[nt]);
        }
        __syncthreads();
        if (tid == 0 && c + 2 < 16) {
            int nc = c + 2;
            MB_EXPECT(mb, STG_BYTES);
            bulkcp(Asm,         d_hpk + nc * 16384, 16384, mb);
            bulkcp(Asm + 16384, wblk + (size_t)nc * 65536, 65536, mb);
        }
    }

    // ---- fused epilogue: online lse + dual argmax, direct on fragments ----
    const float* gub = gu + ((size_t)t * BN) * VOCABN + vBase;
#pragma unroll
    for (int h = 0; h < 2; h++) {
        int row = mrow + (lane >> 2) + 8 * h;
        const float* gur = gub + (size_t)row * VOCABN;
        float mx = -1e30f, se = 0.f;
        float bk = -1e30f, bkl = 0.f, bg = -1e30f, bgl = 0.f;
        int bki = 0x7fffffff, bgi = 0x7fffffff;
#pragma unroll
        for (int nt = 0; nt < 8; nt++) {
            int col = ncol + nt * 8 + 2 * (lane & 3);
            float2 uu = *(const float2*)(gur + col);
            float uv[2]; uv[0] = uu.x; uv[1] = uu.y;
#pragma unroll
            for (int e = 0; e < 2; e++) {
                int v = vBase + col + e;
                float logit = acc[nt][2 * h + e] + bo[col + e];
                float u = fminf(fmaxf(uv[e], 1e-12f), 1.0f);
                float g = -logf(-logf(u));
                if (logit > mx) { se = se * expf(mx - logit) + 1.f; mx = logit; }
                else            { se += expf(logit - mx); }
                float key = logit + g;
                if (key > bk || (key == bk && v < bki)) { bk = key; bki = v; bkl = logit; }
                if (g   > bg || (g   == bg && v < bgi)) { bg = g;   bgi = v; bgl = logit; }
            }
        }
#pragma unroll
        for (int s = 1; s < 4; s <<= 1) {
            float omx  = __shfl_xor_sync(0xffffffffu, mx,  s);
            float ose  = __shfl_xor_sync(0xffffffffu, se,  s);
            float obk  = __shfl_xor_sync(0xffffffffu, bk,  s);
            float obkl = __shfl_xor_sync(0xffffffffu, bkl, s);
            int   obki = __shfl_xor_sync(0xffffffffu, bki, s);
            float obg  = __shfl_xor_sync(0xffffffffu, bg,  s);
            float obgl = __shfl_xor_sync(0xffffffffu, bgl, s);
            int   obgi = __shfl_xor_sync(0xffffffffu, bgi, s);
            float nm = fmaxf(mx, omx);
            se = se * expf(mx - nm) + ose * expf(omx - nm); mx = nm;
            if (obk > bk || (obk == bk && obki < bki)) { bk = obk; bki = obki; bkl = obkl; }
            if (obg > bg || (obg == bg && obgi < bgi)) { bg = obg; bgi = obgi; bgl = obgl; }
        }
        if ((lane & 3) == 0) {
            Part p; p.mx = mx; p.se = se; p.bk = bk; p.bkl = bkl;
            p.bg = bg; p.bgl = bgl; p.bki = bki; p.bgi = bgi;
            parts[row * 4 + nw] = p;
        }
    }
    __syncthreads();
    if (tid < 64) {
        Part p = parts[tid * 4 + 0];
#pragma unroll
        for (int w = 1; w < 4; w++) mergeP(p, parts[tid * 4 + w]);
        d_part[blockIdx.x * BN + tid] = p;
    }

    // ---- last-CTA fused finalize (counts only logits blocks) ----
    __threadfence();
    __syncthreads();
    if (tid == 0) {
        u32 prev = atomicAdd(&d_cnt, 1u);
        isLast = (prev == NT2 - 1) ? 1u : 0u;
    }
    __syncthreads();
    if (isLast) {
        __threadfence();
        int b = tid >> 3, k = tid & 7;
        Part p; p.mx = -1e30f; p.se = 0.f; p.bk = -1e30f; p.bkl = 0.f;
        p.bg = -1e30f; p.bgl = 0.f; p.bki = 0x7fffffff; p.bgi = 0x7fffffff;
        for (int j = k; j < NT2; j += 8) mergeP(p, d_part[j * BN + b]);
#pragma unroll
        for (int s = 1; s < 8; s <<= 1) {
            Part o;
            o.mx  = __shfl_xor_sync(0xffffffffu, p.mx,  s);
            o.se  = __shfl_xor_sync(0xffffffffu, p.se,  s);
            o.bk  = __shfl_xor_sync(0xffffffffu, p.bk,  s);
            o.bkl = __shfl_xor_sync(0xffffffffu, p.bkl, s);
            o.bki = __shfl_xor_sync(0xffffffffu, p.bki, s);
            o.bg  = __shfl_xor_sync(0xffffffffu, p.bg,  s);
            o.bgl = __shfl_xor_sync(0xffffffffu, p.bgl, s);
            o.bgi = __shfl_xor_sync(0xffffffffu, p.bgi, s);
            mergeP(p, o);
        }
        if (k == 0) {
            float lse = p.mx + logf(p.se);
            bool draw = eps_u[t * BN + b] <= 0.5f;
            int idx = draw ? p.bgi : p.bki;
            float logit_at = draw ? p.bgl : p.bkl;
            float lp = logit_at - lse;
            float behav = draw ? -logf((float)VOCABN) : lp;
            float off = fminf(fmaxf(expf(behav), 0.001f), 1.0f);
            float corr = expf(lp) / off;
            out[b * SEQN + t]                 = (float)idx;
            out[BN * SEQN + b * SEQN + t]     = corr;
            out[2 * BN * SEQN + b * SEQN + t] = lp;
            d_samp[b] = idx;
        }
        __syncthreads();
        if (tid == 0) atomicExch(&d_cnt, 0u);
    }
}

// ---------------- launch ------------------------------------------------------
extern "C" void kernel_launch(void* const* d_in, const int* in_sizes, int n_in,
                              void* d_out, int out_size) {
    const float* emb   = (const float*)d_in[0];
    const float* w_ih  = (const float*)d_in[1];
    const float* w_hh  = (const float*)d_in[2];
    const float* b_ih  = (const float*)d_in[3];
    const float* b_hh  = (const float*)d_in[4];
    const float* w_out = (const float*)d_in[5];
    const float* b_out = (const float*)d_in[6];
    const float* gu    = (const float*)d_in[7];
    const float* eps_u = (const float*)d_in[8];
    float* out = (float*)d_out;

    cudaFuncSetAttribute(k_logits, cudaFuncAttributeMaxDynamicSharedMemorySize, SMEM_LOG);

    k_init<<<3072, 256>>>();
    k_splitpack<<<8192, 256>>>(w_out);
    for (int t = 0; t < SEQN; t++) {
        int hin = t & 1;
        k_gi<<<dim3(24, 4), 256>>>(emb, w_ih);
        k_combine<<<256, 256>>>(b_ih, b_hh, hin);
        // logits(t) + gh(t+1) on otherwise-idle SMs; hbn = (t+1)&1 = hin^1
        k_logits<<<NT2 + GHB, 512, SMEM_LOG>>>(b_out, gu, eps_u, w_hh, out,
                                               t, hin ^ 1, (t + 1 < SEQN) ? 1 : 0);
    }
}

// round 15
// speedup vs baseline: 1.0931x; 1.0931x over previous
#include <cuda_runtime.h>
#include <cuda_bf16.h>
#include <math.h>

#define VOCABN 32000
#define EMBN   512
#define HIDN   1024
#define BN     64
#define SEQN   64
#define G3N    3072
#define NT2    125   /* 32000 / 256 vocab tiles */

typedef unsigned long long ull;
typedef unsigned int u32;

struct Part { float mx, se, bk, bkl, bg, bgl; int bki, bgi; };

// ---------------- device scratch (no allocations allowed) -------------------
__device__ float d_h[2][BN * HIDN];
__device__ int   d_samp[BN];
__device__ float d_pgi[2][BN * G3N];
__device__ float d_pgh[4][BN * G3N];
__device__ Part  d_part[NT2 * BN];
__device__ u32   d_cnt;
// packed, SW128-swizzled bf16 tiles for the logits GEMM
// w: [125 tiles][16 chunks][hi 32KB | lo 32KB]  (256 rows x 64 cols per chunk)
__device__ __align__(128) char d_wpk[(size_t)NT2 * 16 * 65536];
// h: [16 chunks][hi 8KB | lo 8KB]               (64 rows x 64 cols per chunk)
__device__ __align__(128) char d_hpk[16 * 16384];

// ---------------- f32x2 packed helpers (sm_103a: 2x FFMA throughput) --------
__device__ __forceinline__ ull pack2(float lo, float hi) {
    ull r; asm("mov.b64 %0, {%1, %2};" : "=l"(r) : "f"(lo), "f"(hi)); return r;
}
__device__ __forceinline__ void unpack2(ull v, float& lo, float& hi) {
    asm("mov.b64 {%0, %1}, %2;" : "=f"(lo), "=f"(hi) : "l"(v));
}
__device__ __forceinline__ void fma2(ull& d, ull a, ull b) {
    asm("fma.rn.f32x2 %0, %1, %2, %0;" : "+l"(d) : "l"(a), "l"(b));
}

// ---------------- mma.sync / bulk-copy helpers -------------------------------
__device__ __forceinline__ u32 smem_u32(const void* p) {
    u32 a; asm("{ .reg .u64 t; cvta.to.shared.u64 t, %1; cvt.u32.u64 %0, t; }"
               : "=r"(a) : "l"(p));
    return a;
}
__device__ __forceinline__ void ldmA4(u32 a, u32* r) {
    asm volatile("ldmatrix.sync.aligned.m8n8.x4.shared.b16 {%0,%1,%2,%3}, [%4];"
                 : "=r"(r[0]), "=r"(r[1]), "=r"(r[2]), "=r"(r[3]) : "r"(a));
}
__device__ __forceinline__ void ldmB2(u32 a, u32* r) {
    asm volatile("ldmatrix.sync.aligned.m8n8.x2.shared.b16 {%0,%1}, [%2];"
                 : "=r"(r[0]), "=r"(r[1]) : "r"(a));
}
__device__ __forceinline__ void mma16816(float* c, const u32* a, const u32* b) {
    asm volatile(
        "mma.sync.aligned.m16n8k16.row.col.f32.bf16.bf16.f32 "
        "{%0,%1,%2,%3}, {%4,%5,%6,%7}, {%8,%9}, {%0,%1,%2,%3};"
        : "+f"(c[0]), "+f"(c[1]), "+f"(c[2]), "+f"(c[3])
        : "r"(a[0]), "r"(a[1]), "r"(a[2]), "r"(a[3]), "r"(b[0]), "r"(b[1]));
}
__device__ __forceinline__ void bulkcp(u32 dst, const void* src, u32 bytes, u32 mbar) {
    asm volatile(
        "cp.async.bulk.shared::cta.global.mbarrier::complete_tx::bytes [%0], [%1], %2, [%3];"
        :: "r"(dst), "l"(src), "r"(bytes), "r"(mbar) : "memory");
}
#define MB_INIT(mbar, cnt) \
    asm volatile("mbarrier.init.shared.b64 [%0], %1;" :: "r"(mbar), "r"(cnt) : "memory")
#define MB_EXPECT(mbar, bytes) \
    asm volatile("mbarrier.arrive.expect_tx.shared.b64 _, [%0], %1;" :: "r"(mbar), "r"(bytes) : "memory")
#define MB_WAIT(mbar, parity) do { \
    asm volatile( \
        "{\n\t.reg .pred P1;\n\t" \
        "WL_%=:\n\t" \
        "mbarrier.try_wait.parity.acquire.cta.shared::cta.b64 P1, [%0], %1, 0x989680;\n\t" \
        "@P1 bra.uni WD_%=;\n\t" \
        "bra.uni WL_%=;\n\t" \
        "WD_%=:\n\t}" \
        :: "r"(mbar), "r"(parity) : "memory"); \
} while (0)

// swizzle: XOR 16B-segment index with (row & 7)
__device__ __forceinline__ u32 swz(int row, int colbyte) {
    return (u32)(row * 128 + (colbyte ^ ((row & 7) << 4)));
}

// ---------------- init ------------------------------------------------------
__global__ void k_init() {
    int i = blockIdx.x * blockDim.x + threadIdx.x;
    if (i < BN * HIDN) d_h[0][i] = 0.f;
    if (i < BN) d_samp[i] = 0;
    if (i == 0) d_cnt = 0;
    if (i < 16 * 16384 / 16) {
        uint4 z; z.x = z.y = z.z = z.w = 0;
        *(uint4*)(d_hpk + i * 16) = z;
    }
}

// ---------------- pack w_out -> chunk-major swizzled bf16 hi/lo --------------
__global__ void k_splitpack(const float* __restrict__ w_out) {
    long n = (long)NT2 * 16 * 256 * 64;
    long i = (long)blockIdx.x * blockDim.x + threadIdx.x;
    long stride = (long)gridDim.x * blockDim.x;
    for (; i < n; i += stride) {
        int k = (int)(i & 63);
        long r2 = i >> 6;   int r = (int)(r2 & 255);
        long c2 = r2 >> 8;  int c = (int)(c2 & 15);
        int v = (int)(c2 >> 4);
        float x = w_out[((size_t)(v * 256 + r)) * HIDN + c * 64 + k];
        __nv_bfloat16 hi = __float2bfloat16_rn(x);
        float l = x - __bfloat162float(hi);
        size_t blk = ((size_t)v * 16 + c) * 65536;
        u32 off = swz(r, k * 2);
        *(__nv_bfloat16*)(d_wpk + blk + off)         = hi;
        *(__nv_bfloat16*)(d_wpk + blk + 32768 + off) = __float2bfloat16_rn(l);
    }
}

// ---------------- fused gates partial GEMMs (fp32 f32x2) --------------------
// grid (24, 6): y<2 -> gi = emb[samp]@w_ih^T (K-split 2 of 256);
//               y>=2 -> gh = h@w_hh^T (K-split 4 of 256)
__global__ __launch_bounds__(256) void k_gates(const float* __restrict__ emb,
                                               const float* __restrict__ w_ih,
                                               const float* __restrict__ w_hh,
                                               int hb) {
    __shared__ int ss[BN];
    __shared__ __align__(16) float As[64][36];
    __shared__ __align__(16) float Bs[32][130];
    int tid = threadIdx.x, tx = tid & 15, ty = tid >> 4;
    int nBase = blockIdx.x * 128;
    int yk = blockIdx.y;
    bool isGi = yk < 2;
    int kBase = (isGi ? yk : (yk - 2)) * 256;
    const float* w = isGi ? w_ih : w_hh;
    int ldw = isGi ? EMBN : HIDN;
    const float* h = d_h[hb];
    if (isGi && tid < BN) ss[tid] = d_samp[tid];
    __syncthreads();

    ull acc[4][4];
    ull z0 = pack2(0.f, 0.f);
#pragma unroll
    for (int i = 0; i < 4; i++)
#pragma unroll
        for (int jj = 0; jj < 4; jj++) acc[i][jj] = z0;

    for (int kt = 0; kt < 8; kt++) {
        int k0 = kBase + kt * 32;
#pragma unroll
        for (int it = 0; it < 2; it++) {
            int idx = tid + it * 256, row = idx >> 3, k4 = (idx & 7) << 2;
            const float* src = isGi ? (emb + (size_t)ss[row] * EMBN + k0 + k4)
                                    : (h + row * HIDN + k0 + k4);
            *(float4*)&As[row][k4] = *(const float4*)src;
        }
#pragma unroll
        for (int it = 0; it < 4; it++) {
            int idx = tid + it * 256, row = idx >> 3, k4 = (idx & 7) << 2;
            float4 v = *(const float4*)(w + (size_t)(nBase + row) * ldw + k0 + k4);
            Bs[k4+0][row] = v.x; Bs[k4+1][row] = v.y;
            Bs[k4+2][row] = v.z; Bs[k4+3][row] = v.w;
        }
        __syncthreads();
#pragma unroll
        for (int kk = 0; kk < 32; kk++) {
            ull a2[4], b2[4];
#pragma unroll
            for (int jj = 0; jj < 4; jj++)
                b2[jj] = *(const ull*)&Bs[kk][2 * (tx + 16 * jj)];
#pragma unroll
            for (int i = 0; i < 4; i++) { float a = As[ty*4+i][kk]; a2[i] = pack2(a, a); }
#pragma unroll
            for (int i = 0; i < 4; i++)
#pragma unroll
                for (int jj = 0; jj < 4; jj++) fma2(acc[i][jj], a2[i], b2[jj]);
        }
        __syncthreads();
    }
    float* dst = isGi ? d_pgi[yk] : d_pgh[yk - 2];
#pragma unroll
    for (int i = 0; i < 4; i++) { int m = ty * 4 + i;
#pragma unroll
        for (int jj = 0; jj < 4; jj++) {
            float lo, hi; unpack2(acc[i][jj], lo, hi);
            float2 vv; vv.x = lo; vv.y = hi;
            *(float2*)&dst[m * G3N + nBase + 2 * (tx + 16 * jj)] = vv;
        }
    }
}

// ---------------- GRU gate combine -> h_new (+ packed bf16 hi/lo) -----------
__global__ void k_combine(const float* __restrict__ b_ih,
                          const float* __restrict__ b_hh, int hb) {
    int idx = blockIdx.x * blockDim.x + threadIdx.x;
    if (idx >= BN * HIDN) return;
    int b = idx >> 10, j = idx & 1023;
    int base = b * G3N;
    float gir = b_ih[j], giz = b_ih[j + HIDN], gin = b_ih[j + 2 * HIDN];
    float ghr = b_hh[j], ghz = b_hh[j + HIDN], ghn = b_hh[j + 2 * HIDN];
#pragma unroll
    for (int ks = 0; ks < 2; ks++) {
        gir += d_pgi[ks][base + j];
        giz += d_pgi[ks][base + j + HIDN];
        gin += d_pgi[ks][base + j + 2 * HIDN];
    }
#pragma unroll
    for (int ks = 0; ks < 4; ks++) {
        ghr += d_pgh[ks][base + j];
        ghz += d_pgh[ks][base + j + HIDN];
        ghn += d_pgh[ks][base + j + 2 * HIDN];
    }
    float r = 1.f / (1.f + expf(-(gir + ghr)));
    float z = 1.f / (1.f + expf(-(giz + ghz)));
    float n = tanhf(gin + r * ghn);
    float hp = d_h[hb][idx];
    float hn = (1.f - z) * n + z * hp;
    d_h[hb ^ 1][idx] = hn;
    __nv_bfloat16 hi = __float2bfloat16_rn(hn);
    float lo = hn - __bfloat162float(hi);
    int chk = j >> 6, kk = j & 63;
    u32 off = swz(b, kk * 2);
    *(__nv_bfloat16*)(d_hpk + chk * 16384 + off)        = hi;
    *(__nv_bfloat16*)(d_hpk + chk * 16384 + 8192 + off) = __float2bfloat16_rn(lo);
}

// ---------------- merge helper ------------------------------------------------
__device__ __forceinline__ void mergeP(Part& a, const Part& o) {
    float nm = fmaxf(a.mx, o.mx);
    a.se = a.se * expf(a.mx - nm) + o.se * expf(o.mx - nm);
    a.mx = nm;
    if (o.bk > a.bk || (o.bk == a.bk && o.bki < a.bki)) { a.bk = o.bk; a.bki = o.bki; a.bkl = o.bkl; }
    if (o.bg > a.bg || (o.bg == a.bg && o.bgi < a.bgi)) { a.bg = o.bg; a.bgi = o.bgi; a.bgl = o.bgl; }
}

// ---------------- logits: bulk-copy pipeline + mma.sync bf16x3 + fused final --
// grid 125, 512 thr = 16 warps (4M x 4N); CTA tile M=64 x N=256, K chunks of 64
#define STG_BYTES 81920
#define OFF_MB   (2 * STG_BYTES)
#define OFF_BO   (OFF_MB + 16)
#define OFF_PART (OFF_BO + 1024 + 16)
#define SMEM_LOG (OFF_PART + 64 * 4 * (int)sizeof(Part))

__global__ __launch_bounds__(512) void k_logits(const float* __restrict__ b_out,
                                                const float* __restrict__ gu,
                                                const float* __restrict__ eps_u,
                                                float* __restrict__ out,
                                                int t) {
    extern __shared__ __align__(128) char smem[];
    __shared__ u32 isLast;
    u32 sbase = smem_u32(smem);
    int tid = threadIdx.x, lane = tid & 31, wid = tid >> 5;
    int mw = wid >> 2, nw = wid & 3;           // 4 x 4 warp grid
    int mrow = mw * 16, ncol = nw * 64;
    int vBase = blockIdx.x * 256;

    float* bo = (float*)(smem + OFF_BO);
    Part* parts = (Part*)(smem + OFF_PART);
    if (tid < 256) bo[tid] = b_out[vBase + tid];
    if (tid == 0) {
        MB_INIT(sbase + OFF_MB, 1u);
        MB_INIT(sbase + OFF_MB + 8, 1u);
    }
    __syncthreads();

    const char* wblk = d_wpk + (size_t)blockIdx.x * 16 * 65536;
    if (tid == 0) {
#pragma unroll
        for (int s = 0; s < 2; s++) {
            u32 mb = sbase + OFF_MB + s * 8;
            MB_EXPECT(mb, STG_BYTES);
            bulkcp(sbase + s * STG_BYTES,         d_hpk + s * 16384, 16384, mb);
            bulkcp(sbase + s * STG_BYTES + 16384, wblk + (size_t)s * 65536, 65536, mb);
        }
    }

    // per-lane ldmatrix address constants (swizzled rows of 128B)
    int lrA = lane & 15;
    u32 xorA = (u32)(lane & 7) << 4;
    u32 colA0 = (u32)((lane >> 4) << 4);       // 0 or 16
    int lrB = lane & 7;
    u32 xorB = (u32)(lane & 7) << 4;
    u32 colB0 = (u32)(((lane >> 3) & 1) << 4); // 0 or 16

    float acc[8][4];
#pragma unroll
    for (int j = 0; j < 8; j++)
#pragma unroll
        for (int k = 0; k < 4; k++) acc[j][k] = 0.f;

    for (int c = 0; c < 16; c++) {
        int st = c & 1;
        u32 mb = sbase + OFF_MB + st * 8;
        MB_WAIT(mb, (c >> 1) & 1);
        u32 Asm = sbase + st * STG_BYTES;
        u32 Bsm = Asm + 16384;
#pragma unroll
        for (int ks = 0; ks < 4; ks++) {
            u32 kb = ks * 32;
            u32 ah[4], al[4], bh[8][2], bl[8][2];
            u32 ra = (u32)((mrow + lrA) * 128) + ((kb + colA0) ^ xorA);
            ldmA4(Asm + ra, ah);
            ldmA4(Asm + 8192 + ra, al);
#pragma unroll
            for (int nt = 0; nt < 8; nt++) {
                u32 rb = (u32)((ncol + nt * 8 + lrB) * 128) + ((kb + colB0) ^ xorB);
                ldmB2(Bsm + rb, bh[nt]);
                ldmB2(Bsm + 32768 + rb, bl[nt]);
            }
#pragma unroll
            for (int nt = 0; nt < 8; nt++) mma16816(acc[nt], ah, bh[nt]);
#pragma unroll
            for (int nt = 0; nt < 8; nt++) mma16816(acc[nt], ah, bl[nt]);
#pragma unroll
            for (int nt = 0; nt < 8; nt++) mma16816(acc[nt], al, bh[nt]);
        }
        __syncthreads();
        if (tid == 0 && c + 2 < 16) {
            int nc = c + 2;
            MB_EXPECT(mb, STG_BYTES);
            bulkcp(Asm,         d_hpk + nc * 16384, 16384, mb);
            bulkcp(Asm + 16384, wblk + (size_t)nc * 65536, 65536, mb);
        }
    }

    // ---- fused epilogue: online lse + dual argmax, direct on fragments ----
    const float* gub = gu + ((size_t)t * BN) * VOCABN + vBase;
#pragma unroll
    for (int h = 0; h < 2; h++) {
        int row = mrow + (lane >> 2) + 8 * h;
        const float* gur = gub + (size_t)row * VOCABN;
        float mx = -1e30f, se = 0.f;
        float bk = -1e30f, bkl = 0.f, bg = -1e30f, bgl = 0.f;
        int bki = 0x7fffffff, bgi = 0x7fffffff;
#pragma unroll
        for (int nt = 0; nt < 8; nt++) {
            int col = ncol + nt * 8 + 2 * (lane & 3);
            float2 uu = *(const float2*)(gur + col);
            float uv[2]; uv[0] = uu.x; uv[1] = uu.y;
#pragma unroll
            for (int e = 0; e < 2; e++) {
                int v = vBase + col + e;
                float logit = acc[nt][2 * h + e] + bo[col + e];
                float u = fminf(fmaxf(uv[e], 1e-12f), 1.0f);
                float g = -logf(-logf(u));
                if (logit > mx) { se = se * expf(mx - logit) + 1.f; mx = logit; }
                else            { se += expf(logit - mx); }
                float key = logit + g;
                if (key > bk || (key == bk && v < bki)) { bk = key; bki = v; bkl = logit; }
                if (g   > bg || (g   == bg && v < bgi)) { bg = g;   bgi = v; bgl = logit; }
            }
        }
#pragma unroll
        for (int s = 1; s < 4; s <<= 1) {
            float omx  = __shfl_xor_sync(0xffffffffu, mx,  s);
            float ose  = __shfl_xor_sync(0xffffffffu, se,  s);
            float obk  = __shfl_xor_sync(0xffffffffu, bk,  s);
            float obkl = __shfl_xor_sync(0xffffffffu, bkl, s);
            int   obki = __shfl_xor_sync(0xffffffffu, bki, s);
            float obg  = __shfl_xor_sync(0xffffffffu, bg,  s);
            float obgl = __shfl_xor_sync(0xffffffffu, bgl, s);
            int   obgi = __shfl_xor_sync(0xffffffffu, bgi, s);
            float nm = fmaxf(mx, omx);
            se = se * expf(mx - nm) + ose * expf(omx - nm); mx = nm;
            if (obk > bk || (obk == bk && obki < bki)) { bk = obk; bki = obki; bkl = obkl; }
            if (obg > bg || (obg == bg && obgi < bgi)) { bg = obg; bgi = obgi; bgl = obgl; }
        }
        if ((lane & 3) == 0) {
            Part p; p.mx = mx; p.se = se; p.bk = bk; p.bkl = bkl;
            p.bg = bg; p.bgl = bgl; p.bki = bki; p.bgi = bgi;
            parts[row * 4 + nw] = p;
        }
    }
    __syncthreads();
    if (tid < 64) {
        Part p = parts[tid * 4 + 0];
#pragma unroll
        for (int w = 1; w < 4; w++) mergeP(p, parts[tid * 4 + w]);
        d_part[blockIdx.x * BN + tid] = p;
    }

    // ---- last-CTA fused finalize (deterministic fixed-order reduction) ----
    __threadfence();
    __syncthreads();
    if (tid == 0) {
        u32 prev = atomicAdd(&d_cnt, 1u);
        isLast = (prev == NT2 - 1) ? 1u : 0u;
    }
    __syncthreads();
    if (isLast) {
        __threadfence();
        int b = tid >> 3, k = tid & 7;    // 64 batches x 8 reducers
        Part p; p.mx = -1e30f; p.se = 0.f; p.bk = -1e30f; p.bkl = 0.f;
        p.bg = -1e30f; p.bgl = 0.f; p.bki = 0x7fffffff; p.bgi = 0x7fffffff;
        for (int j = k; j < NT2; j += 8) mergeP(p, d_part[j * BN + b]);
#pragma unroll
        for (int s = 1; s < 8; s <<= 1) {
            Part o;
            o.mx  = __shfl_xor_sync(0xffffffffu, p.mx,  s);
            o.se  = __shfl_xor_sync(0xffffffffu, p.se,  s);
            o.bk  = __shfl_xor_sync(0xffffffffu, p.bk,  s);
            o.bkl = __shfl_xor_sync(0xffffffffu, p.bkl, s);
            o.bki = __shfl_xor_sync(0xffffffffu, p.bki, s);
            o.bg  = __shfl_xor_sync(0xffffffffu, p.bg,  s);
            o.bgl = __shfl_xor_sync(0xffffffffu, p.bgl, s);
            o.bgi = __shfl_xor_sync(0xffffffffu, p.bgi, s);
            mergeP(p, o);
        }
        if (k == 0) {
            float lse = p.mx + logf(p.se);
            bool draw = eps_u[t * BN + b] <= 0.5f;
            int idx = draw ? p.bgi : p.bki;
            float logit_at = draw ? p.bgl : p.bkl;
            float lp = logit_at - lse;
            float behav = draw ? -logf((float)VOCABN) : lp;
            float off = fminf(fmaxf(expf(behav), 0.001f), 1.0f);
            float corr = expf(lp) / off;
            out[b * SEQN + t]                 = (float)idx;
            out[BN * SEQN + b * SEQN + t]     = corr;
            out[2 * BN * SEQN + b * SEQN + t] = lp;
            d_samp[b] = idx;
        }
        __syncthreads();
        if (tid == 0) atomicExch(&d_cnt, 0u);
    }
}

// ---------------- launch ------------------------------------------------------
extern "C" void kernel_launch(void* const* d_in, const int* in_sizes, int n_in,
                              void* d_out, int out_size) {
    const float* emb   = (const float*)d_in[0];
    const float* w_ih  = (const float*)d_in[1];
    const float* w_hh  = (const float*)d_in[2];
    const float* b_ih  = (const float*)d_in[3];
    const float* b_hh  = (const float*)d_in[4];
    const float* w_out = (const float*)d_in[5];
    const float* b_out = (const float*)d_in[6];
    const float* gu    = (const float*)d_in[7];
    const float* eps_u = (const float*)d_in[8];
    float* out = (float*)d_out;

    cudaFuncSetAttribute(k_logits, cudaFuncAttributeMaxDynamicSharedMemorySize, SMEM_LOG);

    k_init<<<256, 256>>>();
    k_splitpack<<<8192, 256>>>(w_out);
    for (int t = 0; t < SEQN; t++) {
        int hin = t & 1;
        k_gates<<<dim3(24, 6), 256>>>(emb, w_ih, w_hh, hin);
        k_combine<<<256, 256>>>(b_ih, b_hh, hin);
        k_logits<<<NT2, 512, SMEM_LOG>>>(b_out, gu, eps_u, out, t);
    }
}

// round 16
// speedup vs baseline: 1.1808x; 1.0802x over previous
#include <cuda_runtime.h>
#include <cuda_bf16.h>
#include <math.h>

#define VOCABN 32000
#define EMBN   512
#define HIDN   1024
#define BN     64
#define SEQN   64
#define G3N    3072
#define NT2    125   /* 32000 / 256 vocab tiles */

typedef unsigned long long ull;
typedef unsigned int u32;

struct Part { float mx, se, bk, bkl, bg, bgl; int bki, bgi; };

// ---------------- device scratch (no allocations allowed) -------------------
__device__ float d_h[2][BN * HIDN];
__device__ int   d_samp[BN];
__device__ float d_pgi[4][BN * G3N];
__device__ float d_pgh[8][BN * G3N];
__device__ Part  d_part[NT2 * BN];
__device__ u32   d_cnt;
// packed, SW128-swizzled bf16 tiles for the logits GEMM
// w: [125 tiles][16 chunks][hi 32KB | lo 32KB]  (256 rows x 64 cols per chunk)
__device__ __align__(128) char d_wpk[(size_t)NT2 * 16 * 65536];
// h: [16 chunks][hi 8KB | lo 8KB]               (64 rows x 64 cols per chunk)
__device__ __align__(128) char d_hpk[16 * 16384];

// ---------------- f32x2 packed helpers (sm_103a: 2x FFMA throughput) --------
__device__ __forceinline__ ull pack2(float lo, float hi) {
    ull r; asm("mov.b64 %0, {%1, %2};" : "=l"(r) : "f"(lo), "f"(hi)); return r;
}
__device__ __forceinline__ void unpack2(ull v, float& lo, float& hi) {
    asm("mov.b64 {%0, %1}, %2;" : "=f"(lo), "=f"(hi) : "l"(v));
}
__device__ __forceinline__ void fma2(ull& d, ull a, ull b) {
    asm("fma.rn.f32x2 %0, %1, %2, %0;" : "+l"(d) : "l"(a), "l"(b));
}

// ---------------- mma.sync / bulk-copy helpers -------------------------------
__device__ __forceinline__ u32 smem_u32(const void* p) {
    u32 a; asm("{ .reg .u64 t; cvta.to.shared.u64 t, %1; cvt.u32.u64 %0, t; }"
               : "=r"(a) : "l"(p));
    return a;
}
__device__ __forceinline__ void ldmA4(u32 a, u32* r) {
    asm volatile("ldmatrix.sync.aligned.m8n8.x4.shared.b16 {%0,%1,%2,%3}, [%4];"
                 : "=r"(r[0]), "=r"(r[1]), "=r"(r[2]), "=r"(r[3]) : "r"(a));
}
__device__ __forceinline__ void ldmB2(u32 a, u32* r) {
    asm volatile("ldmatrix.sync.aligned.m8n8.x2.shared.b16 {%0,%1}, [%2];"
                 : "=r"(r[0]), "=r"(r[1]) : "r"(a));
}
__device__ __forceinline__ void mma16816(float* c, const u32* a, const u32* b) {
    asm volatile(
        "mma.sync.aligned.m16n8k16.row.col.f32.bf16.bf16.f32 "
        "{%0,%1,%2,%3}, {%4,%5,%6,%7}, {%8,%9}, {%0,%1,%2,%3};"
        : "+f"(c[0]), "+f"(c[1]), "+f"(c[2]), "+f"(c[3])
        : "r"(a[0]), "r"(a[1]), "r"(a[2]), "r"(a[3]), "r"(b[0]), "r"(b[1]));
}
__device__ __forceinline__ void bulkcp(u32 dst, const void* src, u32 bytes, u32 mbar) {
    asm volatile(
        "cp.async.bulk.shared::cta.global.mbarrier::complete_tx::bytes [%0], [%1], %2, [%3];"
        :: "r"(dst), "l"(src), "r"(bytes), "r"(mbar) : "memory");
}
#define MB_INIT(mbar, cnt) \
    asm volatile("mbarrier.init.shared.b64 [%0], %1;" :: "r"(mbar), "r"(cnt) : "memory")
#define MB_EXPECT(mbar, bytes) \
    asm volatile("mbarrier.arrive.expect_tx.shared.b64 _, [%0], %1;" :: "r"(mbar), "r"(bytes) : "memory")
#define MB_WAIT(mbar, parity) do { \
    asm volatile( \
        "{\n\t.reg .pred P1;\n\t" \
        "WL_%=:\n\t" \
        "mbarrier.try_wait.parity.acquire.cta.shared::cta.b64 P1, [%0], %1, 0x989680;\n\t" \
        "@P1 bra.uni WD_%=;\n\t" \
        "bra.uni WL_%=;\n\t" \
        "WD_%=:\n\t}" \
        :: "r"(mbar), "r"(parity) : "memory"); \
} while (0)

// swizzle: XOR 16B-segment index with (row & 7)
__device__ __forceinline__ u32 swz(int row, int colbyte) {
    return (u32)(row * 128 + (colbyte ^ ((row & 7) << 4)));
}

// ---------------- init ------------------------------------------------------
__global__ void k_init() {
    int i = blockIdx.x * blockDim.x + threadIdx.x;
    if (i < BN * HIDN) d_h[0][i] = 0.f;
    if (i < BN) d_samp[i] = 0;
    if (i == 0) d_cnt = 0;
    if (i < 16 * 16384 / 16) {
        uint4 z; z.x = z.y = z.z = z.w = 0;
        *(uint4*)(d_hpk + i * 16) = z;
    }
}

// ---------------- pack w_out -> chunk-major swizzled bf16 hi/lo --------------
__global__ void k_splitpack(const float* __restrict__ w_out) {
    long n = (long)NT2 * 16 * 256 * 64;
    long i = (long)blockIdx.x * blockDim.x + threadIdx.x;
    long stride = (long)gridDim.x * blockDim.x;
    for (; i < n; i += stride) {
        int k = (int)(i & 63);
        long r2 = i >> 6;   int r = (int)(r2 & 255);
        long c2 = r2 >> 8;  int c = (int)(c2 & 15);
        int v = (int)(c2 >> 4);
        float x = w_out[((size_t)(v * 256 + r)) * HIDN + c * 64 + k];
        __nv_bfloat16 hi = __float2bfloat16_rn(x);
        float l = x - __bfloat162float(hi);
        size_t blk = ((size_t)v * 16 + c) * 65536;
        u32 off = swz(r, k * 2);
        *(__nv_bfloat16*)(d_wpk + blk + off)         = hi;
        *(__nv_bfloat16*)(d_wpk + blk + 32768 + off) = __float2bfloat16_rn(l);
    }
}

// ---------------- fused gates partial GEMMs (fp32 f32x2) --------------------
// grid (24, 12): y<4 -> gi = emb[samp]@w_ih^T (K-split 4); y>=4 -> gh (K-split 8)
__global__ __launch_bounds__(256) void k_gates(const float* __restrict__ emb,
                                               const float* __restrict__ w_ih,
                                               const float* __restrict__ w_hh,
                                               int hb) {
    __shared__ int ss[BN];
    __shared__ __align__(16) float As[64][36];
    __shared__ __align__(16) float Bs[32][130];
    int tid = threadIdx.x, tx = tid & 15, ty = tid >> 4;
    int nBase = blockIdx.x * 128;
    int yk = blockIdx.y;
    bool isGi = yk < 4;
    int kBase = (isGi ? yk : (yk - 4)) * 128;
    const float* w = isGi ? w_ih : w_hh;
    int ldw = isGi ? EMBN : HIDN;
    const float* h = d_h[hb];
    if (isGi && tid < BN) ss[tid] = d_samp[tid];
    __syncthreads();

    ull acc[4][4];
    ull z0 = pack2(0.f, 0.f);
#pragma unroll
    for (int i = 0; i < 4; i++)
#pragma unroll
        for (int jj = 0; jj < 4; jj++) acc[i][jj] = z0;

    for (int kt = 0; kt < 4; kt++) {
        int k0 = kBase + kt * 32;
#pragma unroll
        for (int it = 0; it < 2; it++) {
            int idx = tid + it * 256, row = idx >> 3, k4 = (idx & 7) << 2;
            const float* src = isGi ? (emb + (size_t)ss[row] * EMBN + k0 + k4)
                                    : (h + row * HIDN + k0 + k4);
            *(float4*)&As[row][k4] = *(const float4*)src;
        }
#pragma unroll
        for (int it = 0; it < 4; it++) {
            int idx = tid + it * 256, row = idx >> 3, k4 = (idx & 7) << 2;
            float4 v = *(const float4*)(w + (size_t)(nBase + row) * ldw + k0 + k4);
            Bs[k4+0][row] = v.x; Bs[k4+1][row] = v.y;
            Bs[k4+2][row] = v.z; Bs[k4+3][row] = v.w;
        }
        __syncthreads();
#pragma unroll
        for (int kk = 0; kk < 32; kk++) {
            ull a2[4], b2[4];
#pragma unroll
            for (int jj = 0; jj < 4; jj++)
                b2[jj] = *(const ull*)&Bs[kk][2 * (tx + 16 * jj)];
#pragma unroll
            for (int i = 0; i < 4; i++) { float a = As[ty*4+i][kk]; a2[i] = pack2(a, a); }
#pragma unroll
            for (int i = 0; i < 4; i++)
#pragma unroll
                for (int jj = 0; jj < 4; jj++) fma2(acc[i][jj], a2[i], b2[jj]);
        }
        __syncthreads();
    }
    float* dst = isGi ? d_pgi[yk] : d_pgh[yk - 4];
#pragma unroll
    for (int i = 0; i < 4; i++) { int m = ty * 4 + i;
#pragma unroll
        for (int jj = 0; jj < 4; jj++) {
            float lo, hi; unpack2(acc[i][jj], lo, hi);
            float2 vv; vv.x = lo; vv.y = hi;
            *(float2*)&dst[m * G3N + nBase + 2 * (tx + 16 * jj)] = vv;
        }
    }
}

// ---------------- GRU gate combine -> h_new (+ packed bf16 hi/lo) -----------
__global__ void k_combine(const float* __restrict__ b_ih,
                          const float* __restrict__ b_hh, int hb) {
    int idx = blockIdx.x * blockDim.x + threadIdx.x;
    if (idx >= BN * HIDN) return;
    int b = idx >> 10, j = idx & 1023;
    int base = b * G3N;
    float gir = b_ih[j], giz = b_ih[j + HIDN], gin = b_ih[j + 2 * HIDN];
    float ghr = b_hh[j], ghz = b_hh[j + HIDN], ghn = b_hh[j + 2 * HIDN];
#pragma unroll
    for (int ks = 0; ks < 4; ks++) {
        gir += d_pgi[ks][base + j];
        giz += d_pgi[ks][base + j + HIDN];
        gin += d_pgi[ks][base + j + 2 * HIDN];
    }
#pragma unroll
    for (int ks = 0; ks < 8; ks++) {
        ghr += d_pgh[ks][base + j];
        ghz += d_pgh[ks][base + j + HIDN];
        ghn += d_pgh[ks][base + j + 2 * HIDN];
    }
    float r = 1.f / (1.f + expf(-(gir + ghr)));
    float z = 1.f / (1.f + expf(-(giz + ghz)));
    float n = tanhf(gin + r * ghn);
    float hp = d_h[hb][idx];
    float hn = (1.f - z) * n + z * hp;
    d_h[hb ^ 1][idx] = hn;
    __nv_bfloat16 hi = __float2bfloat16_rn(hn);
    float lo = hn - __bfloat162float(hi);
    int chk = j >> 6, kk = j & 63;
    u32 off = swz(b, kk * 2);
    *(__nv_bfloat16*)(d_hpk + chk * 16384 + off)        = hi;
    *(__nv_bfloat16*)(d_hpk + chk * 16384 + 8192 + off) = __float2bfloat16_rn(lo);
}

// ---------------- merge helper ------------------------------------------------
__device__ __forceinline__ void mergeP(Part& a, const Part& o) {
    float nm = fmaxf(a.mx, o.mx);
    a.se = a.se * expf(a.mx - nm) + o.se * expf(o.mx - nm);
    a.mx = nm;
    if (o.bk > a.bk || (o.bk == a.bk && o.bki < a.bki)) { a.bk = o.bk; a.bki = o.bki; a.bkl = o.bkl; }
    if (o.bg > a.bg || (o.bg == a.bg && o.bgi < a.bgi)) { a.bg = o.bg; a.bgi = o.bgi; a.bgl = o.bgl; }
}

// ---------------- logits: bulk-copy pipeline + mma.sync bf16x3 + fused final --
// grid 125, 512 thr = 16 warps (4M x 4N); CTA tile M=64 x N=256, K chunks of 64
#define STG_BYTES 81920
#define OFF_MB   (2 * STG_BYTES)
#define OFF_BO   (OFF_MB + 16)
#define OFF_PART (OFF_BO + 1024 + 16)
#define SMEM_LOG (OFF_PART + 64 * 4 * (int)sizeof(Part))

__global__ __launch_bounds__(512) void k_logits(const float* __restrict__ b_out,
                                                const float* __restrict__ gu,
                                                const float* __restrict__ eps_u,
                                                float* __restrict__ out,
                                                int t) {
    extern __shared__ __align__(128) char smem[];
    __shared__ u32 isLast;
    u32 sbase = smem_u32(smem);
    int tid = threadIdx.x, lane = tid & 31, wid = tid >> 5;
    int mw = wid >> 2, nw = wid & 3;           // 4 x 4 warp grid
    int mrow = mw * 16, ncol = nw * 64;
    int vBase = blockIdx.x * 256;

    float* bo = (float*)(smem + OFF_BO);
    Part* parts = (Part*)(smem + OFF_PART);
    if (tid < 256) bo[tid] = b_out[vBase + tid];
    if (tid == 0) {
        MB_INIT(sbase + OFF_MB, 1u);
        MB_INIT(sbase + OFF_MB + 8, 1u);
    }
    __syncthreads();

    // ---- early register preload of this thread's gu values (independent of
    // everything in the kernel; latency hidden under the whole mainloop) ----
    float2 guv[2][8];
    {
        const float* gub = gu + ((size_t)t * BN) * VOCABN + vBase;
#pragma unroll
        for (int h = 0; h < 2; h++) {
            int row = mrow + (lane >> 2) + 8 * h;
            const float* gur = gub + (size_t)row * VOCABN;
#pragma unroll
            for (int nt = 0; nt < 8; nt++) {
                int col = ncol + nt * 8 + 2 * (lane & 3);
                guv[h][nt] = *(const float2*)(gur + col);
            }
        }
    }

    const char* wblk = d_wpk + (size_t)blockIdx.x * 16 * 65536;
    if (tid == 0) {
#pragma unroll
        for (int s = 0; s < 2; s++) {
            u32 mb = sbase + OFF_MB + s * 8;
            MB_EXPECT(mb, STG_BYTES);
            bulkcp(sbase + s * STG_BYTES,         d_hpk + s * 16384, 16384, mb);
            bulkcp(sbase + s * STG_BYTES + 16384, wblk + (size_t)s * 65536, 65536, mb);
        }
    }

    // per-lane ldmatrix address constants (swizzled rows of 128B)
    int lrA = lane & 15;
    u32 xorA = (u32)(lane & 7) << 4;
    u32 colA0 = (u32)((lane >> 4) << 4);       // 0 or 16
    int lrB = lane & 7;
    u32 xorB = (u32)(lane & 7) << 4;
    u32 colB0 = (u32)(((lane >> 3) & 1) << 4); // 0 or 16

    float acc[8][4];
#pragma unroll
    for (int j = 0; j < 8; j++)
#pragma unroll
        for (int k = 0; k < 4; k++) acc[j][k] = 0.f;

    for (int c = 0; c < 16; c++) {
        int st = c & 1;
        u32 mb = sbase + OFF_MB + st * 8;
        MB_WAIT(mb, (c >> 1) & 1);
        u32 Asm = sbase + st * STG_BYTES;
        u32 Bsm = Asm + 16384;
#pragma unroll
        for (int ks = 0; ks < 4; ks++) {
            u32 kb = ks * 32;
            u32 ah[4], al[4], bh[8][2], bl[8][2];
            u32 ra = (u32)((mrow + lrA) * 128) + ((kb + colA0) ^ xorA);
            ldmA4(Asm + ra, ah);
            ldmA4(Asm + 8192 + ra, al);
#pragma unroll
            for (int nt = 0; nt < 8; nt++) {
                u32 rb = (u32)((ncol + nt * 8 + lrB) * 128) + ((kb + colB0) ^ xorB);
                ldmB2(Bsm + rb, bh[nt]);
                ldmB2(Bsm + 32768 + rb, bl[nt]);
            }
#pragma unroll
            for (int nt = 0; nt < 8; nt++) mma16816(acc[nt], ah, bh[nt]);
#pragma unroll
            for (int nt = 0; nt < 8; nt++) mma16816(acc[nt], ah, bl[nt]);
#pragma unroll
            for (int nt = 0; nt < 8; nt++) mma16816(acc[nt], al, bh[nt]);
        }
        __syncthreads();
        if (tid == 0 && c + 2 < 16) {
            int nc = c + 2;
            MB_EXPECT(mb, STG_BYTES);
            bulkcp(Asm,         d_hpk + nc * 16384, 16384, mb);
            bulkcp(Asm + 16384, wblk + (size_t)nc * 65536, 65536, mb);
        }
    }

    // ---- fused epilogue: online lse + dual argmax, gu from registers ----
#pragma unroll
    for (int h = 0; h < 2; h++) {
        int row = mrow + (lane >> 2) + 8 * h;
        float mx = -1e30f, se = 0.f;
        float bk = -1e30f, bkl = 0.f, bg = -1e30f, bgl = 0.f;
        int bki = 0x7fffffff, bgi = 0x7fffffff;
#pragma unroll
        for (int nt = 0; nt < 8; nt++) {
            int col = ncol + nt * 8 + 2 * (lane & 3);
            float uv[2]; uv[0] = guv[h][nt].x; uv[1] = guv[h][nt].y;
#pragma unroll
            for (int e = 0; e < 2; e++) {
                int v = vBase + col + e;
                float logit = acc[nt][2 * h + e] + bo[col + e];
                float u = fminf(fmaxf(uv[e], 1e-12f), 1.0f);
                float g = -logf(-logf(u));
                if (logit > mx) { se = se * expf(mx - logit) + 1.f; mx = logit; }
                else            { se += expf(logit - mx); }
                float key = logit + g;
                if (key > bk || (key == bk && v < bki)) { bk = key; bki = v; bkl = logit; }
                if (g   > bg || (g   == bg && v < bgi)) { bg = g;   bgi = v; bgl = logit; }
            }
        }
#pragma unroll
        for (int s = 1; s < 4; s <<= 1) {
            float omx  = __shfl_xor_sync(0xffffffffu, mx,  s);
            float ose  = __shfl_xor_sync(0xffffffffu, se,  s);
            float obk  = __shfl_xor_sync(0xffffffffu, bk,  s);
            float obkl = __shfl_xor_sync(0xffffffffu, bkl, s);
            int   obki = __shfl_xor_sync(0xffffffffu, bki, s);
            float obg  = __shfl_xor_sync(0xffffffffu, bg,  s);
            float obgl = __shfl_xor_sync(0xffffffffu, bgl, s);
            int   obgi = __shfl_xor_sync(0xffffffffu, bgi, s);
            float nm = fmaxf(mx, omx);
            se = se * expf(mx - nm) + ose * expf(omx - nm); mx = nm;
            if (obk > bk || (obk == bk && obki < bki)) { bk = obk; bki = obki; bkl = obkl; }
            if (obg > bg || (obg == bg && obgi < bgi)) { bg = obg; bgi = obgi; bgl = obgl; }
        }
        if ((lane & 3) == 0) {
            Part p; p.mx = mx; p.se = se; p.bk = bk; p.bkl = bkl;
            p.bg = bg; p.bgl = bgl; p.bki = bki; p.bgi = bgi;
            parts[row * 4 + nw] = p;
        }
    }
    __syncthreads();
    if (tid < 64) {
        Part p = parts[tid * 4 + 0];
#pragma unroll
        for (int w = 1; w < 4; w++) mergeP(p, parts[tid * 4 + w]);
        d_part[blockIdx.x * BN + tid] = p;
    }

    // ---- last-CTA fused finalize (deterministic fixed-order reduction) ----
    __threadfence();
    __syncthreads();
    if (tid == 0) {
        u32 prev = atomicAdd(&d_cnt, 1u);
        isLast = (prev == NT2 - 1) ? 1u : 0u;
    }
    __syncthreads();
    if (isLast) {
        __threadfence();
        int b = tid >> 3, k = tid & 7;    // 64 batches x 8 reducers
        Part p; p.mx = -1e30f; p.se = 0.f; p.bk = -1e30f; p.bkl = 0.f;
        p.bg = -1e30f; p.bgl = 0.f; p.bki = 0x7fffffff; p.bgi = 0x7fffffff;
        for (int j = k; j < NT2; j += 8) mergeP(p, d_part[j * BN + b]);
#pragma unroll
        for (int s = 1; s < 8; s <<= 1) {
            Part o;
            o.mx  = __shfl_xor_sync(0xffffffffu, p.mx,  s);
            o.se  = __shfl_xor_sync(0xffffffffu, p.se,  s);
            o.bk  = __shfl_xor_sync(0xffffffffu, p.bk,  s);
            o.bkl = __shfl_xor_sync(0xffffffffu, p.bkl, s);
            o.bki = __shfl_xor_sync(0xffffffffu, p.bki, s);
            o.bg  = __shfl_xor_sync(0xffffffffu, p.bg,  s);
            o.bgl = __shfl_xor_sync(0xffffffffu, p.bgl, s);
            o.bgi = __shfl_xor_sync(0xffffffffu, p.bgi, s);
            mergeP(p, o);
        }
        if (k == 0) {
            float lse = p.mx + logf(p.se);
            bool draw = eps_u[t * BN + b] <= 0.5f;
            int idx = draw ? p.bgi : p.bki;
            float logit_at = draw ? p.bgl : p.bkl;
            float lp = logit_at - lse;
            float behav = draw ? -logf((float)VOCABN) : lp;
            float off = fminf(fmaxf(expf(behav), 0.001f), 1.0f);
            float corr = expf(lp) / off;
            out[b * SEQN + t]                 = (float)idx;
            out[BN * SEQN + b * SEQN + t]     = corr;
            out[2 * BN * SEQN + b * SEQN + t] = lp;
            d_samp[b] = idx;
        }
        __syncthreads();
        if (tid == 0) atomicExch(&d_cnt, 0u);
    }
}

// ---------------- launch ------------------------------------------------------
extern "C" void kernel_launch(void* const* d_in, const int* in_sizes, int n_in,
                              void* d_out, int out_size) {
    const float* emb   = (const float*)d_in[0];
    const float* w_ih  = (const float*)d_in[1];
    const float* w_hh  = (const float*)d_in[2];
    const float* b_ih  = (const float*)d_in[3];
    const float* b_hh  = (const float*)d_in[4];
    const float* w_out = (const float*)d_in[5];
    const float* b_out = (const float*)d_in[6];
    const float* gu    = (const float*)d_in[7];
    const float* eps_u = (const float*)d_in[8];
    float* out = (float*)d_out;

    cudaFuncSetAttribute(k_logits, cudaFuncAttributeMaxDynamicSharedMemorySize, SMEM_LOG);

    k_init<<<256, 256>>>();
    k_splitpack<<<8192, 256>>>(w_out);
    for (int t = 0; t < SEQN; t++) {
        int hin = t & 1;
        k_gates<<<dim3(24, 12), 256>>>(emb, w_ih, w_hh, hin);
        k_combine<<<256, 256>>>(b_ih, b_hh, hin);
        k_logits<<<NT2, 512, SMEM_LOG>>>(b_out, gu, eps_u, out, t);
    }
}

// round 17
// speedup vs baseline: 1.2011x; 1.0172x over previous
#include <cuda_runtime.h>
#include <cuda_bf16.h>
#include <math.h>

#define VOCABN 32000
#define EMBN   512
#define HIDN   1024
#define BN     64
#define SEQN   64
#define G3N    3072
#define NT2    125   /* 32000 / 256 vocab tiles */

typedef unsigned long long ull;
typedef unsigned int u32;

struct Part { float mx, se, bk, bkl, bg, bgl; int bki, bgi; };

// ---------------- device scratch (no allocations allowed) -------------------
__device__ float d_h[2][BN * HIDN];
__device__ int   d_samp[BN];
__device__ float d_pgi[4][BN * G3N];
__device__ float d_pgh[8][BN * G3N];
__device__ Part  d_part[NT2 * BN];
__device__ u32   d_cnt;
// packed, SW128-swizzled bf16 tiles for the logits GEMM
// w: [125 tiles][16 chunks][hi 32KB | lo 32KB]  (256 rows x 64 cols per chunk)
__device__ __align__(128) char d_wpk[(size_t)NT2 * 16 * 65536];
// h: [16 chunks][hi 8KB | lo 8KB]               (64 rows x 64 cols per chunk)
__device__ __align__(128) char d_hpk[16 * 16384];

// ---------------- f32x2 packed helpers (sm_103a: 2x FFMA throughput) --------
__device__ __forceinline__ ull pack2(float lo, float hi) {
    ull r; asm("mov.b64 %0, {%1, %2};" : "=l"(r) : "f"(lo), "f"(hi)); return r;
}
__device__ __forceinline__ void unpack2(ull v, float& lo, float& hi) {
    asm("mov.b64 {%0, %1}, %2;" : "=f"(lo), "=f"(hi) : "l"(v));
}
__device__ __forceinline__ void fma2(ull& d, ull a, ull b) {
    asm("fma.rn.f32x2 %0, %1, %2, %0;" : "+l"(d) : "l"(a), "l"(b));
}

// ---------------- mma.sync / bulk-copy helpers -------------------------------
__device__ __forceinline__ u32 smem_u32(const void* p) {
    u32 a; asm("{ .reg .u64 t; cvta.to.shared.u64 t, %1; cvt.u32.u64 %0, t; }"
               : "=r"(a) : "l"(p));
    return a;
}
__device__ __forceinline__ void ldmA4(u32 a, u32* r) {
    asm volatile("ldmatrix.sync.aligned.m8n8.x4.shared.b16 {%0,%1,%2,%3}, [%4];"
                 : "=r"(r[0]), "=r"(r[1]), "=r"(r[2]), "=r"(r[3]) : "r"(a));
}
__device__ __forceinline__ void ldmB2(u32 a, u32* r) {
    asm volatile("ldmatrix.sync.aligned.m8n8.x2.shared.b16 {%0,%1}, [%2];"
                 : "=r"(r[0]), "=r"(r[1]) : "r"(a));
}
__device__ __forceinline__ void mma16816(float* c, const u32* a, const u32* b) {
    asm volatile(
        "mma.sync.aligned.m16n8k16.row.col.f32.bf16.bf16.f32 "
        "{%0,%1,%2,%3}, {%4,%5,%6,%7}, {%8,%9}, {%0,%1,%2,%3};"
        : "+f"(c[0]), "+f"(c[1]), "+f"(c[2]), "+f"(c[3])
        : "r"(a[0]), "r"(a[1]), "r"(a[2]), "r"(a[3]), "r"(b[0]), "r"(b[1]));
}
__device__ __forceinline__ void bulkcp(u32 dst, const void* src, u32 bytes, u32 mbar) {
    asm volatile(
        "cp.async.bulk.shared::cta.global.mbarrier::complete_tx::bytes [%0], [%1], %2, [%3];"
        :: "r"(dst), "l"(src), "r"(bytes), "r"(mbar) : "memory");
}
#define MB_INIT(mbar, cnt) \
    asm volatile("mbarrier.init.shared.b64 [%0], %1;" :: "r"(mbar), "r"(cnt) : "memory")
#define MB_EXPECT(mbar, bytes) \
    asm volatile("mbarrier.arrive.expect_tx.shared.b64 _, [%0], %1;" :: "r"(mbar), "r"(bytes) : "memory")
#define MB_WAIT(mbar, parity) do { \
    asm volatile( \
        "{\n\t.reg .pred P1;\n\t" \
        "WL_%=:\n\t" \
        "mbarrier.try_wait.parity.acquire.cta.shared::cta.b64 P1, [%0], %1, 0x989680;\n\t" \
        "@P1 bra.uni WD_%=;\n\t" \
        "bra.uni WL_%=;\n\t" \
        "WD_%=:\n\t}" \
        :: "r"(mbar), "r"(parity) : "memory"); \
} while (0)

// swizzle: XOR 16B-segment index with (row & 7)
__device__ __forceinline__ u32 swz(int row, int colbyte) {
    return (u32)(row * 128 + (colbyte ^ ((row & 7) << 4)));
}

// ---------------- init ------------------------------------------------------
__global__ void k_init() {
    int i = blockIdx.x * blockDim.x + threadIdx.x;
    if (i < BN * HIDN) d_h[0][i] = 0.f;
    if (i < BN) d_samp[i] = 0;
    if (i == 0) d_cnt = 0;
    if (i < 16 * 16384 / 16) {
        uint4 z; z.x = z.y = z.z = z.w = 0;
        *(uint4*)(d_hpk + i * 16) = z;
    }
}

// ---------------- pack w_out -> chunk-major swizzled bf16 hi/lo --------------
__global__ void k_splitpack(const float* __restrict__ w_out) {
    long n = (long)NT2 * 16 * 256 * 64;
    long i = (long)blockIdx.x * blockDim.x + threadIdx.x;
    long stride = (long)gridDim.x * blockDim.x;
    for (; i < n; i += stride) {
        int k = (int)(i & 63);
        long r2 = i >> 6;   int r = (int)(r2 & 255);
        long c2 = r2 >> 8;  int c = (int)(c2 & 15);
        int v = (int)(c2 >> 4);
        float x = w_out[((size_t)(v * 256 + r)) * HIDN + c * 64 + k];
        __nv_bfloat16 hi = __float2bfloat16_rn(x);
        float l = x - __bfloat162float(hi);
        size_t blk = ((size_t)v * 16 + c) * 65536;
        u32 off = swz(r, k * 2);
        *(__nv_bfloat16*)(d_wpk + blk + off)         = hi;
        *(__nv_bfloat16*)(d_wpk + blk + 32768 + off) = __float2bfloat16_rn(l);
    }
}

// ---------------- fused gates partial GEMMs (fp32 f32x2) --------------------
// grid (24, 12): y<4 -> gi = emb[samp]@w_ih^T (K-split 4); y>=4 -> gh (K-split 8)
__global__ __launch_bounds__(256) void k_gates(const float* __restrict__ emb,
                                               const float* __restrict__ w_ih,
                                               const float* __restrict__ w_hh,
                                               int hb) {
    __shared__ int ss[BN];
    __shared__ __align__(16) float As[64][36];
    __shared__ __align__(16) float Bs[32][130];
    int tid = threadIdx.x, tx = tid & 15, ty = tid >> 4;
    int nBase = blockIdx.x * 128;
    int yk = blockIdx.y;
    bool isGi = yk < 4;
    int kBase = (isGi ? yk : (yk - 4)) * 128;
    const float* w = isGi ? w_ih : w_hh;
    int ldw = isGi ? EMBN : HIDN;
    const float* h = d_h[hb];
    if (isGi && tid < BN) ss[tid] = d_samp[tid];
    __syncthreads();

    ull acc[4][4];
    ull z0 = pack2(0.f, 0.f);
#pragma unroll
    for (int i = 0; i < 4; i++)
#pragma unroll
        for (int jj = 0; jj < 4; jj++) acc[i][jj] = z0;

    for (int kt = 0; kt < 4; kt++) {
        int k0 = kBase + kt * 32;
#pragma unroll
        for (int it = 0; it < 2; it++) {
            int idx = tid + it * 256, row = idx >> 3, k4 = (idx & 7) << 2;
            const float* src = isGi ? (emb + (size_t)ss[row] * EMBN + k0 + k4)
                                    : (h + row * HIDN + k0 + k4);
            *(float4*)&As[row][k4] = *(const float4*)src;
        }
#pragma unroll
        for (int it = 0; it < 4; it++) {
            int idx = tid + it * 256, row = idx >> 3, k4 = (idx & 7) << 2;
            float4 v = *(const float4*)(w + (size_t)(nBase + row) * ldw + k0 + k4);
            Bs[k4+0][row] = v.x; Bs[k4+1][row] = v.y;
            Bs[k4+2][row] = v.z; Bs[k4+3][row] = v.w;
        }
        __syncthreads();
#pragma unroll
        for (int kk = 0; kk < 32; kk++) {
            ull a2[4], b2[4];
#pragma unroll
            for (int jj = 0; jj < 4; jj++)
                b2[jj] = *(const ull*)&Bs[kk][2 * (tx + 16 * jj)];
#pragma unroll
            for (int i = 0; i < 4; i++) { float a = As[ty*4+i][kk]; a2[i] = pack2(a, a); }
#pragma unroll
            for (int i = 0; i < 4; i++)
#pragma unroll
                for (int jj = 0; jj < 4; jj++) fma2(acc[i][jj], a2[i], b2[jj]);
        }
        __syncthreads();
    }
    float* dst = isGi ? d_pgi[yk] : d_pgh[yk - 4];
#pragma unroll
    for (int i = 0; i < 4; i++) { int m = ty * 4 + i;
#pragma unroll
        for (int jj = 0; jj < 4; jj++) {
            float lo, hi; unpack2(acc[i][jj], lo, hi);
            float2 vv; vv.x = lo; vv.y = hi;
            *(float2*)&dst[m * G3N + nBase + 2 * (tx + 16 * jj)] = vv;
        }
    }
}

// ---------------- GRU gate combine -> h_new (+ packed bf16 hi/lo) -----------
__global__ void k_combine(const float* __restrict__ b_ih,
                          const float* __restrict__ b_hh, int hb) {
    int idx = blockIdx.x * blockDim.x + threadIdx.x;
    if (idx >= BN * HIDN) return;
    int b = idx >> 10, j = idx & 1023;
    int base = b * G3N;
    float gir = b_ih[j], giz = b_ih[j + HIDN], gin = b_ih[j + 2 * HIDN];
    float ghr = b_hh[j], ghz = b_hh[j + HIDN], ghn = b_hh[j + 2 * HIDN];
#pragma unroll
    for (int ks = 0; ks < 4; ks++) {
        gir += d_pgi[ks][base + j];
        giz += d_pgi[ks][base + j + HIDN];
        gin += d_pgi[ks][base + j + 2 * HIDN];
    }
#pragma unroll
    for (int ks = 0; ks < 8; ks++) {
        ghr += d_pgh[ks][base + j];
        ghz += d_pgh[ks][base + j + HIDN];
        ghn += d_pgh[ks][base + j + 2 * HIDN];
    }
    float r = 1.f / (1.f + expf(-(gir + ghr)));
    float z = 1.f / (1.f + expf(-(giz + ghz)));
    float n = tanhf(gin + r * ghn);
    float hp = d_h[hb][idx];
    float hn = (1.f - z) * n + z * hp;
    d_h[hb ^ 1][idx] = hn;
    __nv_bfloat16 hi = __float2bfloat16_rn(hn);
    float lo = hn - __bfloat162float(hi);
    int chk = j >> 6, kk = j & 63;
    u32 off = swz(b, kk * 2);
    *(__nv_bfloat16*)(d_hpk + chk * 16384 + off)        = hi;
    *(__nv_bfloat16*)(d_hpk + chk * 16384 + 8192 + off) = __float2bfloat16_rn(lo);
}

// ---------------- merge helper ------------------------------------------------
__device__ __forceinline__ void mergeP(Part& a, const Part& o) {
    float nm = fmaxf(a.mx, o.mx);
    a.se = a.se * expf(a.mx - nm) + o.se * expf(o.mx - nm);
    a.mx = nm;
    if (o.bk > a.bk || (o.bk == a.bk && o.bki < a.bki)) { a.bk = o.bk; a.bki = o.bki; a.bkl = o.bkl; }
    if (o.bg > a.bg || (o.bg == a.bg && o.bgi < a.bgi)) { a.bg = o.bg; a.bgi = o.bgi; a.bgl = o.bgl; }
}

// ---------------- logits: bulk-copy pipeline + mma.sync bf16x3 + fused final --
// grid 125, 512 thr = 16 warps (4M x 4N); CTA tile M=64 x N=256, K chunks of 64
#define STG_BYTES 81920
#define OFF_MB   (2 * STG_BYTES)
#define OFF_BO   (OFF_MB + 16)
#define OFF_PART (OFF_BO + 1024 + 16)
#define SMEM_LOG (OFF_PART + 64 * 4 * (int)sizeof(Part))

__global__ __launch_bounds__(512) void k_logits(const float* __restrict__ b_out,
                                                const float* __restrict__ gu,
                                                const float* __restrict__ eps_u,
                                                float* __restrict__ out,
                                                int t) {
    extern __shared__ __align__(128) char smem[];
    __shared__ u32 isLast;
    u32 sbase = smem_u32(smem);
    int tid = threadIdx.x, lane = tid & 31, wid = tid >> 5;
    int mw = wid >> 2, nw = wid & 3;           // 4 x 4 warp grid
    int mrow = mw * 16, ncol = nw * 64;
    int vBase = blockIdx.x * 256;

    float* bo = (float*)(smem + OFF_BO);
    Part* parts = (Part*)(smem + OFF_PART);
    if (tid < 256) bo[tid] = b_out[vBase + tid];
    if (tid == 0) {
        MB_INIT(sbase + OFF_MB, 1u);
        MB_INIT(sbase + OFF_MB + 8, 1u);
    }
    __syncthreads();

    // ---- early register preload of this thread's gu values (independent of
    // everything in the kernel; latency hidden under the whole mainloop) ----
    float2 guv[2][8];
    {
        const float* gub = gu + ((size_t)t * BN) * VOCABN + vBase;
#pragma unroll
        for (int h = 0; h < 2; h++) {
            int row = mrow + (lane >> 2) + 8 * h;
            const float* gur = gub + (size_t)row * VOCABN;
#pragma unroll
            for (int nt = 0; nt < 8; nt++) {
                int col = ncol + nt * 8 + 2 * (lane & 3);
                guv[h][nt] = *(const float2*)(gur + col);
            }
        }
    }

    const char* wblk = d_wpk + (size_t)blockIdx.x * 16 * 65536;
    if (tid == 0) {
#pragma unroll
        for (int s = 0; s < 2; s++) {
            u32 mb = sbase + OFF_MB + s * 8;
            MB_EXPECT(mb, STG_BYTES);
            bulkcp(sbase + s * STG_BYTES,         d_hpk + s * 16384, 16384, mb);
            bulkcp(sbase + s * STG_BYTES + 16384, wblk + (size_t)s * 65536, 65536, mb);
        }
    }

    // per-lane ldmatrix address constants (swizzled rows of 128B)
    int lrA = lane & 15;
    u32 xorA = (u32)(lane & 7) << 4;
    u32 colA0 = (u32)((lane >> 4) << 4);       // 0 or 16
    int lrB = lane & 7;
    u32 xorB = (u32)(lane & 7) << 4;
    u32 colB0 = (u32)(((lane >> 3) & 1) << 4); // 0 or 16

    float acc[8][4];
#pragma unroll
    for (int j = 0; j < 8; j++)
#pragma unroll
        for (int k = 0; k < 4; k++) acc[j][k] = 0.f;

    for (int c = 0; c < 16; c++) {
        int st = c & 1;
        u32 mb = sbase + OFF_MB + st * 8;
        MB_WAIT(mb, (c >> 1) & 1);
        u32 Asm = sbase + st * STG_BYTES;
        u32 Bsm = Asm + 16384;
#pragma unroll
        for (int ks = 0; ks < 4; ks++) {
            u32 kb = ks * 32;
            u32 ah[4], al[4], bh[8][2], bl[8][2];
            u32 ra = (u32)((mrow + lrA) * 128) + ((kb + colA0) ^ xorA);
            ldmA4(Asm + ra, ah);
            ldmA4(Asm + 8192 + ra, al);
#pragma unroll
            for (int nt = 0; nt < 8; nt++) {
                u32 rb = (u32)((ncol + nt * 8 + lrB) * 128) + ((kb + colB0) ^ xorB);
                ldmB2(Bsm + rb, bh[nt]);
                ldmB2(Bsm + 32768 + rb, bl[nt]);
            }
#pragma unroll
            for (int nt = 0; nt < 8; nt++) mma16816(acc[nt], ah, bh[nt]);
#pragma unroll
            for (int nt = 0; nt < 8; nt++) mma16816(acc[nt], ah, bl[nt]);
#pragma unroll
            for (int nt = 0; nt < 8; nt++) mma16816(acc[nt], al, bh[nt]);
        }
        __syncthreads();
        if (tid == 0 && c + 2 < 16) {
            int nc = c + 2;
            MB_EXPECT(mb, STG_BYTES);
            bulkcp(Asm,         d_hpk + nc * 16384, 16384, mb);
            bulkcp(Asm + 16384, wblk + (size_t)nc * 65536, 65536, mb);
        }
    }

    // ---- fused epilogue: online lse + dual argmax, gu from registers ----
    // Fast-math policy: inner logf ACCURATE (u->1 catastrophic amplification),
    // outer log + online exp FAST (continuous outputs, ~1e-7 abs error).
#pragma unroll
    for (int h = 0; h < 2; h++) {
        int row = mrow + (lane >> 2) + 8 * h;
        float mx = -1e30f, se = 0.f;
        float bk = -1e30f, bkl = 0.f, bg = -1e30f, bgl = 0.f;
        int bki = 0x7fffffff, bgi = 0x7fffffff;
#pragma unroll
        for (int nt = 0; nt < 8; nt++) {
            int col = ncol + nt * 8 + 2 * (lane & 3);
            float uv[2]; uv[0] = guv[h][nt].x; uv[1] = guv[h][nt].y;
#pragma unroll
            for (int e = 0; e < 2; e++) {
                int v = vBase + col + e;
                float logit = acc[nt][2 * h + e] + bo[col + e];
                float u = fminf(fmaxf(uv[e], 1e-12f), 1.0f);
                float g = -__logf(-logf(u));
                if (logit > mx) { se = se * __expf(mx - logit) + 1.f; mx = logit; }
                else            { se += __expf(logit - mx); }
                float key = logit + g;
                if (key > bk || (key == bk && v < bki)) { bk = key; bki = v; bkl = logit; }
                if (g   > bg || (g   == bg && v < bgi)) { bg = g;   bgi = v; bgl = logit; }
            }
        }
#pragma unroll
        for (int s = 1; s < 4; s <<= 1) {
            float omx  = __shfl_xor_sync(0xffffffffu, mx,  s);
            float ose  = __shfl_xor_sync(0xffffffffu, se,  s);
            float obk  = __shfl_xor_sync(0xffffffffu, bk,  s);
            float obkl = __shfl_xor_sync(0xffffffffu, bkl, s);
            int   obki = __shfl_xor_sync(0xffffffffu, bki, s);
            float obg  = __shfl_xor_sync(0xffffffffu, bg,  s);
            float obgl = __shfl_xor_sync(0xffffffffu, bgl, s);
            int   obgi = __shfl_xor_sync(0xffffffffu, bgi, s);
            float nm = fmaxf(mx, omx);
            se = se * expf(mx - nm) + ose * expf(omx - nm); mx = nm;
            if (obk > bk || (obk == bk && obki < bki)) { bk = obk; bki = obki; bkl = obkl; }
            if (obg > bg || (obg == bg && obgi < bgi)) { bg = obg; bgi = obgi; bgl = obgl; }
        }
        if ((lane & 3) == 0) {
            Part p; p.mx = mx; p.se = se; p.bk = bk; p.bkl = bkl;
            p.bg = bg; p.bgl = bgl; p.bki = bki; p.bgi = bgi;
            parts[row * 4 + nw] = p;
        }
    }
    __syncthreads();
    if (tid < 64) {
        Part p = parts[tid * 4 + 0];
#pragma unroll
        for (int w = 1; w < 4; w++) mergeP(p, parts[tid * 4 + w]);
        d_part[blockIdx.x * BN + tid] = p;
    }

    // ---- last-CTA fused finalize (deterministic fixed-order reduction) ----
    __threadfence();
    __syncthreads();
    if (tid == 0) {
        u32 prev = atomicAdd(&d_cnt, 1u);
        isLast = (prev == NT2 - 1) ? 1u : 0u;
    }
    __syncthreads();
    if (isLast) {
        __threadfence();
        int b = tid >> 3, k = tid & 7;    // 64 batches x 8 reducers
        Part p; p.mx = -1e30f; p.se = 0.f; p.bk = -1e30f; p.bkl = 0.f;
        p.bg = -1e30f; p.bgl = 0.f; p.bki = 0x7fffffff; p.bgi = 0x7fffffff;
        for (int j = k; j < NT2; j += 8) mergeP(p, d_part[j * BN + b]);
#pragma unroll
        for (int s = 1; s < 8; s <<= 1) {
            Part o;
            o.mx  = __shfl_xor_sync(0xffffffffu, p.mx,  s);
            o.se  = __shfl_xor_sync(0xffffffffu, p.se,  s);
            o.bk  = __shfl_xor_sync(0xffffffffu, p.bk,  s);
            o.bkl = __shfl_xor_sync(0xffffffffu, p.bkl, s);
            o.bki = __shfl_xor_sync(0xffffffffu, p.bki, s);
            o.bg  = __shfl_xor_sync(0xffffffffu, p.bg,  s);
            o.bgl = __shfl_xor_sync(0xffffffffu, p.bgl, s);
            o.bgi = __shfl_xor_sync(0xffffffffu, p.bgi, s);
            mergeP(p, o);
        }
        if (k == 0) {
            float lse = p.mx + logf(p.se);
            bool draw = eps_u[t * BN + b] <= 0.5f;
            int idx = draw ? p.bgi : p.bki;
            float logit_at = draw ? p.bgl : p.bkl;
            float lp = logit_at - lse;
            float behav = draw ? -logf((float)VOCABN) : lp;
            float off = fminf(fmaxf(expf(behav), 0.001f), 1.0f);
            float corr = expf(lp) / off;
            out[b * SEQN + t]                 = (float)idx;
            out[BN * SEQN + b * SEQN + t]     = corr;
            out[2 * BN * SEQN + b * SEQN + t] = lp;
            d_samp[b] = idx;
        }
        __syncthreads();
        if (tid == 0) atomicExch(&d_cnt, 0u);
    }
}

// ---------------- launch ------------------------------------------------------
extern "C" void kernel_launch(void* const* d_in, const int* in_sizes, int n_in,
                              void* d_out, int out_size) {
    const float* emb   = (const float*)d_in[0];
    const float* w_ih  = (const float*)d_in[1];
    const float* w_hh  = (const float*)d_in[2];
    const float* b_ih  = (const float*)d_in[3];
    const float* b_hh  = (const float*)d_in[4];
    const float* w_out = (const float*)d_in[5];
    const float* b_out = (const float*)d_in[6];
    const float* gu    = (const float*)d_in[7];
    const float* eps_u = (const float*)d_in[8];
    float* out = (float*)d_out;

    cudaFuncSetAttribute(k_logits, cudaFuncAttributeMaxDynamicSharedMemorySize, SMEM_LOG);

    k_init<<<256, 256>>>();
    k_splitpack<<<8192, 256>>>(w_out);
    for (int t = 0; t < SEQN; t++) {
        int hin = t & 1;
        k_gates<<<dim3(24, 12), 256>>>(emb, w_ih, w_hh, hin);
        k_combine<<<256, 256>>>(b_ih, b_hh, hin);
        k_logits<<<NT2, 512, SMEM_LOG>>>(b_out, gu, eps_u, out, t);
    }
}